// round 1
// baseline (speedup 1.0000x reference)
#include <cuda_runtime.h>
#include <cstdint>

#define N_TYPES 95
#define EMB 128
#define TILE 128

// Precomputed tables (device globals: no allocation allowed)
__device__ float    g_PT[N_TYPES * 256];   // [z][0:128]=emb@W1^T + b_dense, [z][128:256]=emb@W2^T
__device__ unsigned g_W3T[EMB * EMB];      // W3 transposed to [k][i], tf32 bit patterns

__device__ __forceinline__ float silu_f(float x) {
    return __fdividef(x, 1.0f + __expf(-x));
}
__device__ __forceinline__ unsigned to_tf32(float x) {
    unsigned u; asm("cvt.rna.tf32.f32 %0, %1;" : "=r"(u) : "f"(x)); return u;
}
__device__ __forceinline__ void mma_tf32(float c[4],
                                         unsigned a0, unsigned a1, unsigned a2, unsigned a3,
                                         unsigned b0, unsigned b1) {
    asm volatile(
        "mma.sync.aligned.m16n8k8.row.col.f32.tf32.tf32.f32 "
        "{%0,%1,%2,%3}, {%4,%5,%6,%7}, {%8,%9}, {%0,%1,%2,%3};"
        : "+f"(c[0]), "+f"(c[1]), "+f"(c[2]), "+f"(c[3])
        : "r"(a0), "r"(a1), "r"(a2), "r"(a3), "r"(b0), "r"(b1));
}

// ---------------------------------------------------------------------------
// Precompute: PT[95][256] (node GEMM collapsed over atom types) + W3 transpose
// Blocks 0..94: PT rows.  Blocks 95..158: W3T (tf32).
// ---------------------------------------------------------------------------
__global__ void precompute_kernel(const float* __restrict__ emb,
                                  const float* __restrict__ Wd,
                                  const float* __restrict__ bd) {
    int b = blockIdx.x, t = threadIdx.x;
    if (b < N_TYPES) {
        __shared__ float er[EMB];
        if (t < EMB) er[t] = emb[b * EMB + t];
        __syncthreads();
        int i = t & 127, half = t >> 7;
        const float4* w4 = (const float4*)(Wd + (size_t)i * 384 + half * 128);
        float acc = (half == 0) ? bd[i] : 0.0f;   // fold b_dense into PT1
        #pragma unroll
        for (int k4 = 0; k4 < 32; k4++) {
            float4 w = w4[k4];
            acc += er[k4*4+0]*w.x + er[k4*4+1]*w.y + er[k4*4+2]*w.z + er[k4*4+3]*w.w;
        }
        g_PT[b * 256 + half * 128 + i] = acc;
    } else {
        int idx = (b - N_TYPES) * 256 + t;        // 0..16383
        int k = idx >> 7, i = idx & 127;
        g_W3T[idx] = to_tf32(Wd[(size_t)i * 384 + 256 + k]);
    }
}

// ---------------------------------------------------------------------------
// Main fused kernel: persistent CTAs, one 128-edge tile per loop iteration.
// SMEM: W3 (tf32, stride 136 for conflict-free B-frag loads), full PT table
// (stride 258), rbf tile, W_rbf, b_rbf, z gathers.
// ---------------------------------------------------------------------------
#define W3S_WORDS   (128 * 136)        // 17408
#define PTS_WORDS   (N_TYPES * 258)    // 24510
#define SMEM_WORDS  (W3S_WORDS + PTS_WORDS + 768 + 768 + 128 + 256)  // 43838
#define SMEM_BYTES  (SMEM_WORDS * 4)   // 175352

__global__ void __launch_bounds__(256, 1) main_kernel(
    const int* __restrict__ Z, const int* __restrict__ src, const int* __restrict__ dst,
    const float* __restrict__ rbf, const float* __restrict__ dvec,
    const float* __restrict__ Wr, const float* __restrict__ brbf,
    float* __restrict__ out, int E, int nTiles)
{
    extern __shared__ unsigned sm[];
    unsigned* W3s    = sm;
    float*    PTs    = (float*)(sm + W3S_WORDS);
    float*    rbf_s  = PTs + PTS_WORDS;
    float*    Wr_s   = rbf_s + 768;
    float*    brbf_s = Wr_s + 768;
    int*      zs_s   = (int*)(brbf_s + 128);
    int*      zd_s   = zs_s + 128;

    int tid = threadIdx.x;
    // one-time fills (W3 padded stride 136; PT padded stride 258)
    for (int idx = tid; idx < EMB * EMB; idx += 256)
        W3s[(idx >> 7) * 136 + (idx & 127)] = g_W3T[idx];
    for (int idx = tid; idx < N_TYPES * 256; idx += 256)
        PTs[(idx >> 8) * 258 + (idx & 255)] = g_PT[idx];
    for (int idx = tid; idx < 768; idx += 256) Wr_s[idx] = Wr[idx];
    if (tid < 128) brbf_s[tid] = brbf[tid];

    int lane = tid & 31, w = tid >> 5;
    int g = lane >> 2, q = lane & 3;
    int r0 = w * 16 + g;                 // warp w owns rows [16w, 16w+16)
    size_t envBase = (size_t)E * EMB;

    for (int tile = blockIdx.x; tile < nTiles; tile += gridDim.x) {
        int base = tile * TILE;
        __syncthreads();   // previous epilogue readers done before smem refill

        if (tid < 128) {
            int e = base + tid; if (e >= E) e = E - 1;
            zs_s[tid] = Z[src[e]];
            zd_s[tid] = Z[dst[e]];
        } else {
            // envelope * bessel branch (independent of smem)
            int e = base + (tid - 128);
            if (e < E) {
                float x = dvec[e] * 0.2f;              // d / CUTOFF
                float inv = 1.0f / x;
                float x2 = x*x, x4 = x2*x2, x5 = x4*x, x6 = x5*x, x7 = x6*x;
                float env = inv - 28.0f*x5 + 48.0f*x6 - 21.0f*x7;   // p = 6
                float s = env * inv;                   // env(x) * (1/x)
                float* o = out + envBase + (size_t)e * 6;
                const float PIf = 3.14159265358979323846f;
                #pragma unroll
                for (int n = 1; n <= 6; n++) o[n - 1] = s * sinf(((float)n * PIf) * x);
            }
        }
        {
            int lim = E * 6 - base * 6;
            for (int idx = tid; idx < TILE * 6; idx += 256)
                rbf_s[idx] = (idx < lim) ? rbf[base * 6 + idx] : 0.0f;
        }
        __syncthreads();

        float rb0[6], rb1[6];
        #pragma unroll
        for (int j = 0; j < 6; j++) {
            rb0[j] = rbf_s[r0 * 6 + j];
            rb1[j] = rbf_s[(r0 + 8) * 6 + j];
        }

        float c[16][4];
        #pragma unroll
        for (int nt = 0; nt < 16; nt++) { c[nt][0]=0.f; c[nt][1]=0.f; c[nt][2]=0.f; c[nt][3]=0.f; }

        // K loop: compute the 4 needed H = silu(rbf@Wr^T + b) values on the fly
        // (A-fragment in registers), B-fragments from conflict-free padded smem.
        #pragma unroll 2
        for (int k = 0; k < 16; k++) {
            int ca = 8 * k + q;
            const float* wA = Wr_s + ca * 6;
            float pa0 = brbf_s[ca],     pa1 = pa0;
            float pb0 = brbf_s[ca + 4], pb1 = pb0;
            #pragma unroll
            for (int j = 0; j < 6; j++) {
                float wa = wA[j], wb = wA[24 + j];
                pa0 += rb0[j] * wa;  pa1 += rb1[j] * wa;
                pb0 += rb0[j] * wb;  pb1 += rb1[j] * wb;
            }
            unsigned a0 = to_tf32(silu_f(pa0));
            unsigned a1 = to_tf32(silu_f(pa1));
            unsigned a2 = to_tf32(silu_f(pb0));
            unsigned a3 = to_tf32(silu_f(pb1));
            const unsigned* B0 = W3s + (8 * k + q) * 136 + g;
            #pragma unroll
            for (int nt = 0; nt < 16; nt++)
                mma_tf32(c[nt], a0, a1, a2, a3, B0[nt * 8], B0[544 + nt * 8]); // 544 = 4*136
        }

        // epilogue: + PT1[Z[src]] + PT2[Z[dst]] (b_dense folded in), silu, store
        int e0 = base + r0, e1 = e0 + 8;
        const float* p1a = PTs + zs_s[r0] * 258;
        const float* p2a = PTs + zd_s[r0] * 258 + 128;
        const float* p1b = PTs + zs_s[r0 + 8] * 258;
        const float* p2b = PTs + zd_s[r0 + 8] * 258 + 128;
        float* o0 = out + (size_t)e0 * EMB;
        float* o1 = out + (size_t)e1 * EMB;
        bool st0 = (e0 < E), st1 = (e1 < E);
        #pragma unroll
        for (int nt = 0; nt < 16; nt++) {
            int col = nt * 8 + q * 2;
            float2 A1 = *(const float2*)(p1a + col);
            float2 A2 = *(const float2*)(p2a + col);
            float2 B1 = *(const float2*)(p1b + col);
            float2 B2 = *(const float2*)(p2b + col);
            float2 v0, v1;
            v0.x = silu_f(c[nt][0] + A1.x + A2.x);
            v0.y = silu_f(c[nt][1] + A1.y + A2.y);
            v1.x = silu_f(c[nt][2] + B1.x + B2.x);
            v1.y = silu_f(c[nt][3] + B1.y + B2.y);
            if (st0) *(float2*)(o0 + col) = v0;
            if (st1) *(float2*)(o1 + col) = v1;
        }
    }
}

extern "C" void kernel_launch(void* const* d_in, const int* in_sizes, int n_in,
                              void* d_out, int out_size) {
    const int*   Z    = (const int*)d_in[0];
    const int*   src  = (const int*)d_in[1];
    const int*   dst  = (const int*)d_in[2];
    const float* rbf  = (const float*)d_in[3];
    const float* d    = (const float*)d_in[4];
    const float* emb  = (const float*)d_in[5];
    const float* Wr   = (const float*)d_in[6];
    const float* brbf = (const float*)d_in[7];
    const float* Wd   = (const float*)d_in[8];
    const float* bd   = (const float*)d_in[9];
    int E = in_sizes[1];
    int nTiles = (E + TILE - 1) / TILE;

    precompute_kernel<<<N_TYPES + 64, 256>>>(emb, Wd, bd);

    cudaFuncSetAttribute(main_kernel, cudaFuncAttributeMaxDynamicSharedMemorySize, SMEM_BYTES);
    int dev = 0, nsm = 148;
    cudaGetDevice(&dev);
    cudaDeviceGetAttribute(&nsm, cudaDevAttrMultiProcessorCount, dev);

    main_kernel<<<nsm, 256, SMEM_BYTES>>>(Z, src, dst, rbf, d, Wr, brbf,
                                          (float*)d_out, E, nTiles);
}